// round 2
// baseline (speedup 1.0000x reference)
#include <cuda_runtime.h>
#include <math.h>

#define N_USERS 100000
#define N_ITEMS 50000
#define NNZ     1600000
#define BATCH   64
#define ORDER   8

// ---------------- device scratch (no allocation allowed) ----------------
__device__ int   cb_cnt_u[N_USERS];
__device__ int   cb_cnt_i[N_ITEMS];
__device__ int   cb_ptr_u[N_USERS + 1];
__device__ int   cb_ptr_i[N_ITEMS + 1];
__device__ int   cb_cur_u[N_USERS];
__device__ int   cb_cur_i[N_ITEMS];
__device__ int2  cb_csr[NNZ];   // (col_item, val bits)  sorted by user
__device__ int2  cb_csc[NNZ];   // (row_user, val bits)  sorted by item
__device__ float cb_y[(size_t)N_USERS * BATCH];
__device__ float cb_tA[(size_t)N_ITEMS * BATCH];
__device__ float cb_tB[(size_t)N_ITEMS * BATCH];
__device__ float cb_acc[(size_t)N_ITEMS * BATCH];
__device__ int   cb_bsum_u[128];
__device__ int   cb_bsum_i[128];

// ---------------- small utility kernels ----------------
__global__ void cb_zero_counts() {
    int stride = gridDim.x * blockDim.x;
    for (int i = blockIdx.x * blockDim.x + threadIdx.x; i < N_USERS; i += stride) {
        cb_cnt_u[i] = 0;
        if (i < N_ITEMS) cb_cnt_i[i] = 0;
    }
}

__global__ void cb_hist(const int* __restrict__ row, const int* __restrict__ col) {
    int stride = gridDim.x * blockDim.x;
    for (int e = blockIdx.x * blockDim.x + threadIdx.x; e < NNZ; e += stride) {
        atomicAdd(&cb_cnt_u[row[e]], 1);
        atomicAdd(&cb_cnt_i[col[e]], 1);
    }
}

// block-wide exclusive scan (blockDim multiple of 32, <=1024)
__device__ __forceinline__ int cb_block_exscan(int v, int* sh) {
    int tid = threadIdx.x, lane = tid & 31, w = tid >> 5;
    int x = v;
    #pragma unroll
    for (int o = 1; o < 32; o <<= 1) {
        int t = __shfl_up_sync(0xffffffffu, x, o);
        if (lane >= o) x += t;
    }
    if (lane == 31) sh[w] = x;
    __syncthreads();
    if (w == 0) {
        int nw = blockDim.x >> 5;
        int s = (lane < nw) ? sh[lane] : 0;
        #pragma unroll
        for (int o = 1; o < 32; o <<= 1) {
            int t = __shfl_up_sync(0xffffffffu, s, o);
            if (lane >= o) s += t;
        }
        sh[lane] = s;
    }
    __syncthreads();
    int base = (w > 0) ? sh[w - 1] : 0;
    return base + x - v;   // exclusive prefix
}

__global__ void cb_blocksum(const int* __restrict__ cnt, int* __restrict__ bsum, int n) {
    __shared__ int sh[32];
    int i = blockIdx.x * blockDim.x + threadIdx.x;
    int v = (i < n) ? cnt[i] : 0;
    #pragma unroll
    for (int o = 16; o; o >>= 1) v += __shfl_down_sync(0xffffffffu, v, o);
    if ((threadIdx.x & 31) == 0) sh[threadIdx.x >> 5] = v;
    __syncthreads();
    if (threadIdx.x < 32) {
        int nw = blockDim.x >> 5;
        int s = (threadIdx.x < nw) ? sh[threadIdx.x] : 0;
        #pragma unroll
        for (int o = 16; o; o >>= 1) s += __shfl_down_sync(0xffffffffu, s, o);
        if (threadIdx.x == 0) bsum[blockIdx.x] = s;
    }
}

// single block (128 threads): exclusive scan of nb block sums (in place) + total
__global__ void cb_scan_bsums(int* bsum, int nb, int* total_slot) {
    __shared__ int sh[32];
    int v = (threadIdx.x < nb) ? bsum[threadIdx.x] : 0;
    int ex = cb_block_exscan(v, sh);
    if (threadIdx.x < nb) bsum[threadIdx.x] = ex;
    if (threadIdx.x == nb - 1) *total_slot = ex + v;
}

__global__ void cb_scan_final(const int* __restrict__ cnt, const int* __restrict__ bscan,
                              int* __restrict__ ptr, int n) {
    __shared__ int sh[32];
    int i = blockIdx.x * blockDim.x + threadIdx.x;
    int v = (i < n) ? cnt[i] : 0;
    int ex = cb_block_exscan(v, sh);
    if (i < n) ptr[i] = bscan[blockIdx.x] + ex;
}

__global__ void cb_copy_cursors() {
    int stride = gridDim.x * blockDim.x;
    for (int i = blockIdx.x * blockDim.x + threadIdx.x; i < N_USERS; i += stride) {
        cb_cur_u[i] = cb_ptr_u[i];
        if (i < N_ITEMS) cb_cur_i[i] = cb_ptr_i[i];
    }
}

__global__ void cb_scatter(const int* __restrict__ row, const int* __restrict__ col,
                           const float* __restrict__ vals) {
    int stride = gridDim.x * blockDim.x;
    for (int e = blockIdx.x * blockDim.x + threadIdx.x; e < NNZ; e += stride) {
        int r = row[e], c = col[e];
        int vb = __float_as_int(vals[e]);
        int p = atomicAdd(&cb_cur_u[r], 1);
        cb_csr[p] = make_int2(c, vb);
        int q = atomicAdd(&cb_cur_i[c], 1);
        cb_csc[q] = make_int2(r, vb);
    }
}

// signal [64][N_ITEMS] -> cb_tA [N_ITEMS][64]
__global__ void cb_transpose_in(const float* __restrict__ sig) {
    __shared__ float tile[32][33];
    int item = blockIdx.x * 32 + threadIdx.x;   // fast along items for coalesced read
    int b    = blockIdx.y * 32 + threadIdx.y;
    if (item < N_ITEMS)
        tile[threadIdx.y][threadIdx.x] = sig[(size_t)b * N_ITEMS + item];
    __syncthreads();
    int itemw = blockIdx.x * 32 + threadIdx.y;
    int bw    = blockIdx.y * 32 + threadIdx.x;  // fast along batch for coalesced write
    if (itemw < N_ITEMS)
        cb_tA[(size_t)itemw * BATCH + bw] = tile[threadIdx.x][threadIdx.y];
}

// cb_acc [N_ITEMS][64] -> dst [64][N_ITEMS]
__global__ void cb_transpose_out(float* __restrict__ dst) {
    __shared__ float tile[32][33];
    int b    = blockIdx.y * 32 + threadIdx.x;   // fast along batch for coalesced read
    int item = blockIdx.x * 32 + threadIdx.y;
    if (item < N_ITEMS)
        tile[threadIdx.y][threadIdx.x] = cb_acc[(size_t)item * BATCH + b];
    __syncthreads();
    int itemw = blockIdx.x * 32 + threadIdx.x;  // fast along items for coalesced write
    int bw    = blockIdx.y * 32 + threadIdx.y;
    if (itemw < N_ITEMS)
        dst[(size_t)bw * N_ITEMS + itemw] = tile[threadIdx.x][threadIdx.y];
}

// ---------------- SpMM kernels: one warp per output node ----------------
// y[u,:] = sum_e val_e * x[col_e,:]
__global__ __launch_bounds__(256) void cb_spmmA(const float* __restrict__ x) {
    int gw   = (blockIdx.x * blockDim.x + threadIdx.x) >> 5;
    int lane = threadIdx.x & 31;
    if (gw >= N_USERS) return;
    int e = cb_ptr_u[gw], end = cb_ptr_u[gw + 1];
    float a0 = 0.f, a1 = 0.f, b0 = 0.f, b1 = 0.f;
    for (; e + 2 <= end; e += 2) {
        int2 e0 = __ldg(&cb_csr[e]);
        int2 e1 = __ldg(&cb_csr[e + 1]);
        const float* x0 = x + (size_t)e0.x * BATCH;
        const float* x1 = x + (size_t)e1.x * BATCH;
        float v0 = __int_as_float(e0.y), v1 = __int_as_float(e1.y);
        a0 = fmaf(v0, __ldg(x0 + lane),      a0);
        a1 = fmaf(v0, __ldg(x0 + 32 + lane), a1);
        b0 = fmaf(v1, __ldg(x1 + lane),      b0);
        b1 = fmaf(v1, __ldg(x1 + 32 + lane), b1);
    }
    if (e < end) {
        int2 e0 = __ldg(&cb_csr[e]);
        const float* x0 = x + (size_t)e0.x * BATCH;
        float v0 = __int_as_float(e0.y);
        a0 = fmaf(v0, __ldg(x0 + lane),      a0);
        a1 = fmaf(v0, __ldg(x0 + 32 + lane), a1);
    }
    float* yr = cb_y + (size_t)gw * BATCH;
    yr[lane]      = a0 + b0;
    yr[32 + lane] = a1 + b1;
}

// z[i,:] = sum_e val_e * y[row_e,:], returned in (z0,z1) for this lane
__device__ __forceinline__ void cb_gather_z(int item, int lane, float& z0out, float& z1out) {
    int e = cb_ptr_i[item], end = cb_ptr_i[item + 1];
    float a0 = 0.f, a1 = 0.f, b0 = 0.f, b1 = 0.f;
    for (; e + 2 <= end; e += 2) {
        int2 e0 = __ldg(&cb_csc[e]);
        int2 e1 = __ldg(&cb_csc[e + 1]);
        const float* y0 = cb_y + (size_t)e0.x * BATCH;
        const float* y1 = cb_y + (size_t)e1.x * BATCH;
        float v0 = __int_as_float(e0.y), v1 = __int_as_float(e1.y);
        a0 = fmaf(v0, __ldg(y0 + lane),      a0);
        a1 = fmaf(v0, __ldg(y0 + 32 + lane), a1);
        b0 = fmaf(v1, __ldg(y1 + lane),      b0);
        b1 = fmaf(v1, __ldg(y1 + 32 + lane), b1);
    }
    if (e < end) {
        int2 e0 = __ldg(&cb_csc[e]);
        const float* y0 = cb_y + (size_t)e0.x * BATCH;
        float v0 = __int_as_float(e0.y);
        a0 = fmaf(v0, __ldg(y0 + lane),      a0);
        a1 = fmaf(v0, __ldg(y0 + 32 + lane), a1);
    }
    z0out = a0 + b0;
    z1out = a1 + b1;
}

// First step: t1 = s - 2 z ; out = c0*s + c1*t1
__global__ __launch_bounds__(256) void cb_spmmAT_first(const float* __restrict__ s,
                                                       float* __restrict__ t1,
                                                       float c0, float c1) {
    int item = (blockIdx.x * blockDim.x + threadIdx.x) >> 5;
    int lane = threadIdx.x & 31;
    if (item >= N_ITEMS) return;
    float z0, z1;
    cb_gather_z(item, lane, z0, z1);
    size_t i0 = (size_t)item * BATCH + lane;
    size_t i1 = i0 + 32;
    float s0 = s[i0], s1 = s[i1];
    float t10 = fmaf(-2.f, z0, s0);
    float t11 = fmaf(-2.f, z1, s1);
    t1[i0] = t10;  t1[i1] = t11;
    cb_acc[i0] = c0 * s0 + c1 * t10;
    cb_acc[i1] = c0 * s1 + c1 * t11;
}

// Step k: t2 = 2*t1 - 4*z - t0 ; out += ck*t2 ; t2 overwrites t0's buffer
__global__ __launch_bounds__(256) void cb_spmmAT_step(const float* __restrict__ tcur,
                                                      float* __restrict__ tprev,
                                                      float ck) {
    int item = (blockIdx.x * blockDim.x + threadIdx.x) >> 5;
    int lane = threadIdx.x & 31;
    if (item >= N_ITEMS) return;
    float z0, z1;
    cb_gather_z(item, lane, z0, z1);
    size_t i0 = (size_t)item * BATCH + lane;
    size_t i1 = i0 + 32;
    float t1a = tcur[i0], t1b = tcur[i1];
    float t0a = tprev[i0], t0b = tprev[i1];
    float t2a = 2.f * t1a - 4.f * z0 - t0a;
    float t2b = 2.f * t1b - 4.f * z1 - t0b;
    tprev[i0] = t2a;  tprev[i1] = t2b;
    cb_acc[i0] += ck * t2a;
    cb_acc[i1] += ck * t2b;
}

// ---------------- host side ----------------
static inline double cb_rnd3(double v) { return rint(v * 1000.0) / 1000.0; }

static void cb_coeffs(float* cf) {
    const int order = 8, flat = 2;
    double xv[9], tgt[9], nodes[9];
    for (int x = 0; x <= order; x++)
        xv[x] = cb_rnd3(cos((double)(order - x) / order * M_PI));
    for (int i = 0; i <= order; i++) {
        double t = (xv[i] < 0.0) ? pow(-xv[i], (double)flat) * 0.5 + 0.5
                                 : pow(xv[i], (double)flat) * (-0.5) + 0.5;
        tgt[i] = cb_rnd3(t);
    }
    for (int k = 1; k <= order + 1; k++)
        nodes[k - 1] = cos((order + 1 + 0.5 - k) / (double)(order + 1) * M_PI);
    double prev[9], cur[9], nxt[9];
    double c[9];
    double s0 = 0.0, s1 = 0.0;
    for (int i = 0; i <= order; i++) {
        prev[i] = tgt[i];
        cur[i]  = nodes[i] * tgt[i];
        s0 += prev[i];
        s1 += cur[i];
    }
    c[0] = s0 * (2.0 / (order + 1)) / 2.0;
    c[1] = s1 * (2.0 / (order + 1));
    for (int m = 2; m <= order; m++) {
        double sm = 0.0;
        for (int i = 0; i <= order; i++) {
            nxt[i] = nodes[i] * cur[i] * 2.0 - prev[i];
            sm += nxt[i];
        }
        c[m] = sm * (2.0 / (order + 1));
        for (int i = 0; i <= order; i++) { prev[i] = cur[i]; cur[i] = nxt[i]; }
    }
    for (int m = 0; m <= order; m++) cf[m] = (float)c[m];
}

extern "C" void kernel_launch(void* const* d_in, const int* in_sizes, int n_in,
                              void* d_out, int out_size) {
    const float* signal = (const float*)d_in[0];
    const float* vals   = (const float*)d_in[1];
    const int*   row    = (const int*)d_in[2];
    const int*   col    = (const int*)d_in[3];
    float*       out    = (float*)d_out;

    float cf[ORDER + 1];
    cb_coeffs(cf);

    // device pointers to scratch symbols
    float *tA, *tB;
    int *cnt_u, *cnt_i, *ptr_u, *ptr_i, *bsu, *bsi;
    cudaGetSymbolAddress((void**)&tA,    cb_tA);
    cudaGetSymbolAddress((void**)&tB,    cb_tB);
    cudaGetSymbolAddress((void**)&cnt_u, cb_cnt_u);
    cudaGetSymbolAddress((void**)&cnt_i, cb_cnt_i);
    cudaGetSymbolAddress((void**)&ptr_u, cb_ptr_u);
    cudaGetSymbolAddress((void**)&ptr_i, cb_ptr_i);
    cudaGetSymbolAddress((void**)&bsu,   cb_bsum_u);
    cudaGetSymbolAddress((void**)&bsi,   cb_bsum_i);

    const int NB_U = (N_USERS + 1023) / 1024;   // 98
    const int NB_I = (N_ITEMS + 1023) / 1024;   // 49

    // ---- build CSR/CSC ----
    cb_zero_counts<<<256, 256>>>();
    cb_hist<<<2048, 256>>>(row, col);
    cb_blocksum<<<NB_U, 1024>>>(cnt_u, bsu, N_USERS);
    cb_scan_bsums<<<1, 128>>>(bsu, NB_U, ptr_u + N_USERS);
    cb_scan_final<<<NB_U, 1024>>>(cnt_u, bsu, ptr_u, N_USERS);
    cb_blocksum<<<NB_I, 1024>>>(cnt_i, bsi, N_ITEMS);
    cb_scan_bsums<<<1, 128>>>(bsi, NB_I, ptr_i + N_ITEMS);
    cb_scan_final<<<NB_I, 1024>>>(cnt_i, bsi, ptr_i, N_ITEMS);
    cb_copy_cursors<<<256, 256>>>();
    cb_scatter<<<2048, 256>>>(row, col, vals);

    // ---- transpose signal to node-major (t0 = s in tA) ----
    dim3 tb(32, 32);
    dim3 tg((N_ITEMS + 31) / 32, (BATCH + 31) / 32);
    cb_transpose_in<<<tg, tb>>>(signal);

    const int GA = (N_USERS * 32 + 255) / 256;  // warp per user
    const int GI = (N_ITEMS * 32 + 255) / 256;  // warp per item

    // ---- Chebyshev recurrence ----
    cb_spmmA<<<GA, 256>>>(tA);
    cb_spmmAT_first<<<GI, 256>>>(tA, tB, cf[0], cf[1]);
    float* t0p = tA;
    float* t1p = tB;
    for (int k = 2; k <= ORDER; k++) {
        cb_spmmA<<<GA, 256>>>(t1p);
        cb_spmmAT_step<<<GI, 256>>>(t1p, t0p, cf[k]);
        float* tmp = t0p; t0p = t1p; t1p = tmp;   // (t0,t1) <- (t1,t2)
    }

    // ---- final transpose to [BATCH, N_ITEMS] ----
    cb_transpose_out<<<tg, tb>>>(out);
}